// round 1
// baseline (speedup 1.0000x reference)
#include <cuda_runtime.h>

// Problem constants (fixed by the dataset's setup_inputs)
#define Bc      16
#define Nc      64
#define Tc      768
#define MAXAGE  512
#define NJ      17
#define ROW     51            // NJ*3 floats per pose row
#define BN      (Bc * Nc)     // 1024
#define NSLOT   (BN * MAXAGE) // 524288 output slots

// Scratch: inverse index map (output slot -> source t within its (b,n) row, or -1)
__device__ int g_tidx[NSLOT];

// Sparse posetrack->h36m remap: up to 4 (source joint, weight) terms per output joint.
__constant__ int c_src[NJ][4] = {
    {11,12, 0, 0}, {12, 0, 0, 0}, {14, 0, 0, 0}, {16, 0, 0, 0},
    {11, 0, 0, 0}, {13, 0, 0, 0}, {15, 0, 0, 0},
    { 5, 6,11,12}, { 5, 6, 0, 0},
    { 1, 0, 0, 0}, { 2, 0, 0, 0},
    { 5, 0, 0, 0}, { 7, 0, 0, 0}, { 9, 0, 0, 0},
    { 6, 0, 0, 0}, { 8, 0, 0, 0}, {10, 0, 0, 0}};
__constant__ float c_wt[NJ][4] = {
    {0.5f,0.5f,0.f,0.f}, {1.f,0.f,0.f,0.f}, {1.f,0.f,0.f,0.f}, {1.f,0.f,0.f,0.f},
    {1.f,0.f,0.f,0.f}, {1.f,0.f,0.f,0.f}, {1.f,0.f,0.f,0.f},
    {0.25f,0.25f,0.25f,0.25f}, {0.5f,0.5f,0.f,0.f},
    {1.f,0.f,0.f,0.f}, {1.f,0.f,0.f,0.f},
    {1.f,0.f,0.f,0.f}, {1.f,0.f,0.f,0.f}, {1.f,0.f,0.f,0.f},
    {1.f,0.f,0.f,0.f}, {1.f,0.f,0.f,0.f}, {1.f,0.f,0.f,0.f}};

// Kernel 1: reset the inverse index map.
__global__ void fill_tidx_kernel() {
    int i = blockIdx.x * blockDim.x + threadIdx.x;
    if (i < NSLOT) g_tidx[i] = -1;
}

// Kernel 2: scatter t into the (flipped) age slot.
// valid = isfinite(age) && 0 <= age < max_age  (NaN fails both comparisons)
__global__ void scatter_kernel(const float* __restrict__ ages) {
    int i = blockIdx.x * blockDim.x + threadIdx.x;
    if (i >= BN * Tc) return;
    float a = ages[i];
    if (a >= 0.0f && a < (float)MAXAGE) {
        int ai = (int)a;                 // trunc, matches astype(int32)
        int bn = i / Tc;
        int t  = i - bn * Tc;
        // fold the time-axis flip into the index: output slot s reads buf[MAXAGE-1-s]
        g_tidx[bn * MAXAGE + (MAXAGE - 1 - ai)] = t;
    }
}

// Kernel 3: gather + transform + remap + conf-zero, fully coalesced output writes.
#define SLOTS 64           // slots per block; MAXAGE % SLOTS == 0 -> one bn per block
#define GTHREADS 256
__global__ __launch_bounds__(GTHREADS)
void gather_kernel(const float* __restrict__ kp, float* __restrict__ out) {
    __shared__ float sm[SLOTS][ROW];
    __shared__ int   st[SLOTS];
    const int tid = threadIdx.x;
    const int gslot0 = blockIdx.x * SLOTS;          // first global slot of this block
    const int bn = gslot0 / MAXAGE;                 // same for all slots in block

    if (tid < SLOTS) st[tid] = g_tidx[gslot0 + tid];
    __syncthreads();

    // Phase A: load source rows (xy pre-transformed to [-1,1]) into smem.
    const float* __restrict__ kpbase = kp + (size_t)bn * Tc * ROW;
    #pragma unroll 4
    for (int e = tid; e < SLOTS * ROW; e += GTHREADS) {
        int slot = e / ROW;
        int off  = e - slot * ROW;
        int t    = st[slot];
        float v  = 0.0f;
        if (t >= 0) {
            v = __ldg(kpbase + (size_t)t * ROW + off);
            if (off % 3 != 2) v = fmaf(v, 2.0f, -1.0f);   // xy -> [-1,1]; conf untouched
        }
        sm[slot][off] = v;
    }
    __syncthreads();

    // Phase B: sparse remap + conf-zero, write 3 floats per (slot, joint).
    float* __restrict__ obase = out + (size_t)gslot0 * ROW;
    #pragma unroll
    for (int r = tid; r < SLOTS * NJ; r += GTHREADS) {
        int slot = r / NJ;
        int i    = r - slot * NJ;
        float vx = 0.0f, vy = 0.0f, vc = 0.0f;
        #pragma unroll
        for (int k = 0; k < 4; k++) {
            float w = c_wt[i][k];
            int   j = c_src[i][k] * 3;
            vx = fmaf(w, sm[slot][j + 0], vx);
            vy = fmaf(w, sm[slot][j + 1], vy);
            vc = fmaf(w, sm[slot][j + 2], vc);
        }
        if (vc == 0.0f) { vx = 0.0f; vy = 0.0f; }   // zero whole xyc row on zero conf
        float* o = obase + slot * ROW + i * 3;
        o[0] = vx; o[1] = vy; o[2] = vc;
    }
}

extern "C" void kernel_launch(void* const* d_in, const int* in_sizes, int n_in,
                              void* d_out, int out_size) {
    const float* kp   = (const float*)d_in[0];   // [B,N,T,17,3]
    const float* ages = (const float*)d_in[1];   // [B,N,T,1]
    float* out = (float*)d_out;                  // [B,N,MAXAGE,17,3]
    (void)in_sizes; (void)n_in; (void)out_size;

    fill_tidx_kernel<<<(NSLOT + 255) / 256, 256>>>();
    scatter_kernel<<<(BN * Tc + 255) / 256, 256>>>(ages);
    gather_kernel<<<NSLOT / SLOTS, GTHREADS>>>(kp, out);
}

// round 2
// speedup vs baseline: 1.0104x; 1.0104x over previous
#include <cuda_runtime.h>

// Problem constants (fixed by the dataset's setup_inputs)
#define Bc      16
#define Nc      64
#define Tc      768
#define MAXAGE  512
#define NJ      17
#define ROW     51                  // NJ*3 floats per pose row
#define BN      (Bc * Nc)           // 1024
#define NSLOT   (BN * MAXAGE)       // 524288 output slots
#define SLOTS   64                  // slots per block
#define BLKS_PER_BN (MAXAGE / SLOTS) // 8
#define GT      256                 // threads per block

// Sparse posetrack->h36m remap: up to 4 (source joint, weight) terms per output joint.
__constant__ int c_src[NJ][4] = {
    {11,12, 0, 0}, {12, 0, 0, 0}, {14, 0, 0, 0}, {16, 0, 0, 0},
    {11, 0, 0, 0}, {13, 0, 0, 0}, {15, 0, 0, 0},
    { 5, 6,11,12}, { 5, 6, 0, 0},
    { 1, 0, 0, 0}, { 2, 0, 0, 0},
    { 5, 0, 0, 0}, { 7, 0, 0, 0}, { 9, 0, 0, 0},
    { 6, 0, 0, 0}, { 8, 0, 0, 0}, {10, 0, 0, 0}};
__constant__ float c_wt[NJ][4] = {
    {0.5f,0.5f,0.f,0.f}, {1.f,0.f,0.f,0.f}, {1.f,0.f,0.f,0.f}, {1.f,0.f,0.f,0.f},
    {1.f,0.f,0.f,0.f}, {1.f,0.f,0.f,0.f}, {1.f,0.f,0.f,0.f},
    {0.25f,0.25f,0.25f,0.25f}, {0.5f,0.5f,0.f,0.f},
    {1.f,0.f,0.f,0.f}, {1.f,0.f,0.f,0.f},
    {1.f,0.f,0.f,0.f}, {1.f,0.f,0.f,0.f}, {1.f,0.f,0.f,0.f},
    {1.f,0.f,0.f,0.f}, {1.f,0.f,0.f,0.f}, {1.f,0.f,0.f,0.f}};

// One fused kernel: per-block age inversion -> gather+transform -> remap -> float4 store.
__global__ __launch_bounds__(GT)
void tokenizer_kernel(const float* __restrict__ kp,
                      const float* __restrict__ ages,
                      float* __restrict__ out) {
    __shared__ float smA[SLOTS][ROW];        // source rows (transformed xy)
    __shared__ float smB[SLOTS * ROW];       // remapped rows, staged for float4 out
    __shared__ int   st[SLOTS];              // slot -> source t (or -1)

    const int tid = threadIdx.x;
    const int blk = blockIdx.x;
    const int bn  = blk / BLKS_PER_BN;                 // which (b,n)
    const int sb  = (blk % BLKS_PER_BN) * SLOTS;       // first slot (within bn)

    // ---- Phase 0: invert the age map for this block's slot window ----
    if (tid < SLOTS) st[tid] = -1;
    __syncthreads();
    {
        const float* __restrict__ arow = ages + (size_t)bn * Tc;
        #pragma unroll
        for (int t = tid; t < Tc; t += GT) {
            float a = arow[t];
            // valid = isfinite && 0 <= a < max_age  (NaN fails both compares)
            if (a >= 0.0f && a < (float)MAXAGE) {
                int s = (MAXAGE - 1) - (int)a;          // fold time flip into slot
                int sl = s - sb;
                if ((unsigned)sl < (unsigned)SLOTS)
                    atomicMax(&st[sl], t);              // duplicates: last write (max t) wins
            }
        }
    }
    __syncthreads();

    // ---- Phase A: load source rows, xy -> [-1,1], conf untouched ----
    const float* __restrict__ kpbase = kp + (size_t)bn * Tc * ROW;
    #pragma unroll 4
    for (int e = tid; e < SLOTS * ROW; e += GT) {
        int slot = e / ROW;
        int off  = e - slot * ROW;
        int t    = st[slot];
        float v  = 0.0f;
        if (t >= 0) {
            v = __ldg(kpbase + (size_t)t * ROW + off);
            if (off % 3 != 2) v = fmaf(v, 2.0f, -1.0f);
        }
        smA[slot][off] = v;
    }
    __syncthreads();

    // ---- Phase B: sparse joint remap + conf-zero, into smem staging ----
    #pragma unroll
    for (int r = tid; r < SLOTS * NJ; r += GT) {
        int slot = r / NJ;
        int i    = r - slot * NJ;
        float vx = 0.0f, vy = 0.0f, vc = 0.0f;
        #pragma unroll
        for (int k = 0; k < 4; k++) {
            float w = c_wt[i][k];
            int   j = c_src[i][k] * 3;
            vx = fmaf(w, smA[slot][j + 0], vx);
            vy = fmaf(w, smA[slot][j + 1], vy);
            vc = fmaf(w, smA[slot][j + 2], vc);
        }
        if (vc == 0.0f) { vx = 0.0f; vy = 0.0f; }      // zero whole xyc row on zero conf
        float* o = smB + slot * ROW + i * 3;
        o[0] = vx; o[1] = vy; o[2] = vc;
    }
    __syncthreads();

    // ---- Phase C: coalesced float4 stores (13056 B per block, 16B-aligned) ----
    {
        const float4* __restrict__ s4 = (const float4*)smB;
        float4* __restrict__ o4 =
            (float4*)(out + (size_t)(bn * MAXAGE + sb) * ROW);
        #pragma unroll 4
        for (int e = tid; e < (SLOTS * ROW) / 4; e += GT)
            o4[e] = s4[e];
    }
}

extern "C" void kernel_launch(void* const* d_in, const int* in_sizes, int n_in,
                              void* d_out, int out_size) {
    const float* kp   = (const float*)d_in[0];   // [B,N,T,17,3]
    const float* ages = (const float*)d_in[1];   // [B,N,T,1]
    float* out = (float*)d_out;                  // [B,N,MAXAGE,17,3]
    (void)in_sizes; (void)n_in; (void)out_size;

    tokenizer_kernel<<<NSLOT / SLOTS, GT>>>(kp, ages, out);
}

// round 4
// speedup vs baseline: 1.0781x; 1.0670x over previous
#include <cuda_runtime.h>

// Problem constants (fixed by the dataset's setup_inputs)
#define Bc      16
#define Nc      64
#define Tc      768
#define MAXAGE  512
#define NJ      17
#define ROW     51                    // NJ*3 floats per pose row
#define BN      (Bc * Nc)             // 1024
#define NSLOT   (BN * MAXAGE)         // 524288 output slots

#define SLOTS   32                    // slots per gather block
#define GT      128                   // threads per gather block
#define ELEMS   (SLOTS * ROW)         // 1632 floats per block tile
#define PK      13                    // ceil(ELEMS / GT)
#define NJROWS  (SLOTS * NJ)          // 544
#define NQ      (ELEMS / 4)           // 408 float4 per tile (1632 % 4 == 0)

// Scratch: slot -> source t (or -1), per (b,n). 1 MB.
__device__ short g_st[NSLOT];

// Sparse posetrack->h36m remap: up to 4 (source joint, weight) terms per output joint.
__constant__ int c_src[NJ][4] = {
    {11,12, 0, 0}, {12, 0, 0, 0}, {14, 0, 0, 0}, {16, 0, 0, 0},
    {11, 0, 0, 0}, {13, 0, 0, 0}, {15, 0, 0, 0},
    { 5, 6,11,12}, { 5, 6, 0, 0},
    { 1, 0, 0, 0}, { 2, 0, 0, 0},
    { 5, 0, 0, 0}, { 7, 0, 0, 0}, { 9, 0, 0, 0},
    { 6, 0, 0, 0}, { 8, 0, 0, 0}, {10, 0, 0, 0}};
__constant__ float c_wt[NJ][4] = {
    {0.5f,0.5f,0.f,0.f}, {1.f,0.f,0.f,0.f}, {1.f,0.f,0.f,0.f}, {1.f,0.f,0.f,0.f},
    {1.f,0.f,0.f,0.f}, {1.f,0.f,0.f,0.f}, {1.f,0.f,0.f,0.f},
    {0.25f,0.25f,0.25f,0.25f}, {0.5f,0.5f,0.f,0.f},
    {1.f,0.f,0.f,0.f}, {1.f,0.f,0.f,0.f},
    {1.f,0.f,0.f,0.f}, {1.f,0.f,0.f,0.f}, {1.f,0.f,0.f,0.f},
    {1.f,0.f,0.f,0.f}, {1.f,0.f,0.f,0.f}, {1.f,0.f,0.f,0.f}};

// ---------------------------------------------------------------------------
// Kernel 1: invert the age map. One block per (b,n).
// valid = isfinite(age) && 0 <= age < max_age (NaN fails both compares).
// Slot index already flipped: output slot s reads buf[MAXAGE-1-s].
// ---------------------------------------------------------------------------
__global__ __launch_bounds__(256)
void build_st_kernel(const float* __restrict__ ages) {
    __shared__ int st[MAXAGE];
    const int tid = threadIdx.x;
    const int bn  = blockIdx.x;

    #pragma unroll
    for (int i = tid; i < MAXAGE; i += 256) st[i] = -1;
    __syncthreads();

    const float* __restrict__ arow = ages + (size_t)bn * Tc;
    #pragma unroll
    for (int t = tid; t < Tc; t += 256) {
        float a = arow[t];
        if (a >= 0.0f && a < (float)MAXAGE)
            atomicMax(&st[(MAXAGE - 1) - (int)a], t);   // duplicates: last write (max t) wins
    }
    __syncthreads();

    short* __restrict__ g = g_st + (size_t)bn * MAXAGE;
    #pragma unroll
    for (int i = tid; i < MAXAGE; i += 256) g[i] = (short)st[i];
}

// ---------------------------------------------------------------------------
// Kernel 2: gather + transform + remap + float4 store. One block = 32 slots.
// Phase A is register-batched: 13 independent predicated LDGs per thread.
// ---------------------------------------------------------------------------
__global__ __launch_bounds__(GT, 8)
void gather_kernel(const float* __restrict__ kp, float* __restrict__ out) {
    __shared__ float smA[ELEMS];       // source rows (transformed), slot-major
    __shared__ float smB[ELEMS];       // remapped rows, staged for float4 out
    __shared__ int   st[SLOTS];

    const int tid = threadIdx.x;
    const int blk = blockIdx.x;
    const int bn  = blk / (MAXAGE / SLOTS);

    if (tid < SLOTS) st[tid] = (int)g_st[(size_t)blk * SLOTS + tid];
    __syncthreads();

    // ---- Phase A: batched gather ----
    const float* __restrict__ kpbase = kp + (size_t)bn * Tc * ROW;
    int   soff[PK];
    int   goff[PK];
    bool  pred[PK];
    float v[PK];

    #pragma unroll
    for (int k = 0; k < PK; k++) {
        int e     = tid + k * GT;
        bool val  = (e < ELEMS);
        int ec    = val ? e : 0;
        int slot  = ec / ROW;
        int off   = ec - slot * ROW;
        int t     = st[slot];
        pred[k]   = val && (t >= 0);
        goff[k]   = t * ROW + off;
        soff[k]   = (off % 3 != 2) ? e : ~e;   // sign bit encodes "is confidence"
    }
    #pragma unroll
    for (int k = 0; k < PK; k++)
        v[k] = pred[k] ? __ldg(kpbase + goff[k]) : 0.0f;
    #pragma unroll
    for (int k = 0; k < PK; k++) {
        int e = soff[k];
        if (e >= 0) {                                   // xy channel
            if (pred[k]) v[k] = fmaf(v[k], 2.0f, -1.0f);
            smA[e] = v[k];
        } else {                                        // conf channel
            int ei = ~e;
            if (ei < ELEMS) smA[ei] = v[k];
        }
    }
    __syncthreads();

    // ---- Phase B: sparse joint remap + conf-zero into smem staging ----
    #pragma unroll
    for (int r = tid; r < NJROWS; r += GT) {
        int slot = r / NJ;
        int i    = r - slot * NJ;
        const float* __restrict__ s = smA + slot * ROW;
        float vx = 0.0f, vy = 0.0f, vc = 0.0f;
        #pragma unroll
        for (int k = 0; k < 4; k++) {
            float w = c_wt[i][k];
            int   j = c_src[i][k] * 3;
            vx = fmaf(w, s[j + 0], vx);
            vy = fmaf(w, s[j + 1], vy);
            vc = fmaf(w, s[j + 2], vc);
        }
        if (vc == 0.0f) { vx = 0.0f; vy = 0.0f; }       // zero whole xyc row on zero conf
        float* o = smB + slot * ROW + i * 3;
        o[0] = vx; o[1] = vy; o[2] = vc;
    }
    __syncthreads();

    // ---- Phase C: coalesced float4 stores (6528 B per block, 16B-aligned) ----
    {
        const float4* __restrict__ s4 = (const float4*)smB;
        float4* __restrict__ o4 = (float4*)(out + (size_t)blk * ELEMS);
        #pragma unroll
        for (int e = tid; e < NQ; e += GT)
            o4[e] = s4[e];
    }
}

extern "C" void kernel_launch(void* const* d_in, const int* in_sizes, int n_in,
                              void* d_out, int out_size) {
    const float* kp   = (const float*)d_in[0];   // [B,N,T,17,3]
    const float* ages = (const float*)d_in[1];   // [B,N,T,1]
    float* out = (float*)d_out;                  // [B,N,MAXAGE,17,3]
    (void)in_sizes; (void)n_in; (void)out_size;

    build_st_kernel<<<BN, 256>>>(ages);
    gather_kernel<<<NSLOT / SLOTS, GT>>>(kp, out);
}